// round 6
// baseline (speedup 1.0000x reference)
#include <cuda_runtime.h>
#include <cuda_bf16.h>
#include <cstdint>

// Problem constants (fixed by the reference)
#define L_LEN   1024
#define BATCH   16
#define DIM     2048            // K
#define HID     2048
#define NCOL    (3 * HID)       // 6144  (N)
#define MROW    (L_LEN * BATCH) // 16384 (M)

// ---------------------------------------------------------------------------
// Device scratch (static __device__ globals: the sanctioned no-alloc path)
// ---------------------------------------------------------------------------
__device__ float         g_U[(size_t)MROW * NCOL];          // 402.7 MB
__device__ __nv_bfloat16 g_XhiT[(size_t)DIM * MROW];        // 64 MB  (X^T hi)
__device__ __nv_bfloat16 g_XloT[(size_t)DIM * MROW];        // 64 MB  (X^T lo)
__device__ __nv_bfloat16 g_Whi [(size_t)DIM * NCOL];        // 24 MB
__device__ __nv_bfloat16 g_Wlo [(size_t)DIM * NCOL];        // 24 MB

// ---------------------------------------------------------------------------
// Streaming (evict-first) load/store helpers for the write-once/read-once g_U
// ---------------------------------------------------------------------------
__device__ __forceinline__ void stg_cs_f2(float* p, float a, float b) {
    asm volatile("st.global.cs.v2.f32 [%0], {%1, %2};" :: "l"(p), "f"(a), "f"(b) : "memory");
}
__device__ __forceinline__ float ldg_cs_f(const float* p) {
    float v;
    asm volatile("ld.global.cs.f32 %0, [%1];" : "=f"(v) : "l"(p));
    return v;
}

// ---------------------------------------------------------------------------
// Conversion kernels: fp32 -> (bf16 hi, bf16 lo), lo = rn(v - float(hi))
// ---------------------------------------------------------------------------
__global__ __launch_bounds__(256) void conv_w_kernel(const float* __restrict__ w)
{
    size_t i = (size_t)blockIdx.x * blockDim.x + threadIdx.x;
    if (i >= (size_t)DIM * NCOL) return;
    float v = w[i];
    __nv_bfloat16 hi = __float2bfloat16_rn(v);
    float lo = v - __bfloat162float(hi);
    g_Whi[i] = hi;
    g_Wlo[i] = __float2bfloat16_rn(lo);
}

// X [MROW][DIM] -> XhiT/XloT [DIM][MROW] (transpose + split)
__global__ __launch_bounds__(256) void conv_x_kernel(const float* __restrict__ x)
{
    __shared__ float t[32][33];
    const int k0 = blockIdx.x * 32;
    const int m0 = blockIdx.y * 32;
    const int tx = threadIdx.x;        // 0..31
    const int ty = threadIdx.y;        // 0..7

    #pragma unroll
    for (int i = 0; i < 4; i++)
        t[ty + 8 * i][tx] = x[(size_t)(m0 + ty + 8 * i) * DIM + k0 + tx];
    __syncthreads();

    #pragma unroll
    for (int i = 0; i < 4; i++) {
        float v = t[tx][ty + 8 * i];                  // = x[m0+tx][k0+ty+8i]
        __nv_bfloat16 hi = __float2bfloat16_rn(v);
        float lo = v - __bfloat162float(hi);
        size_t o = (size_t)(k0 + ty + 8 * i) * MROW + m0 + tx;
        g_XhiT[o] = hi;
        g_XloT[o] = __float2bfloat16_rn(lo);
    }
}

// ---------------------------------------------------------------------------
// Split-bf16 GEMM:  g_U[M][N] = X[M][K] * W[K][N]  (fp32-accurate via 3 MMAs)
// BM=128, BN=128, BK=16, 256 threads (8 warps, 64x32 warp tiles),
// 3-stage cp.async pipeline, XOR-swizzled smem, ldmatrix.trans + mma.m16n8k16.
// ---------------------------------------------------------------------------
#define BM 128
#define BN 128
#define BK 16
#define NT (DIM / BK)   // 128
#define STAGES 3

__device__ __forceinline__ void cp_async16(uint32_t dst, const void* src) {
    asm volatile("cp.async.ca.shared.global [%0], [%1], 16;\n" :: "r"(dst), "l"(src));
}
__device__ __forceinline__ void cp_commit() {
    asm volatile("cp.async.commit_group;\n" ::: "memory");
}
template<int N> __device__ __forceinline__ void cp_wait() {
    asm volatile("cp.async.wait_group %0;\n" :: "n"(N) : "memory");
}
__device__ __forceinline__ void ldm_x4_trans(uint32_t addr, uint32_t& r0, uint32_t& r1,
                                             uint32_t& r2, uint32_t& r3) {
    asm volatile("ldmatrix.sync.aligned.m8n8.x4.trans.shared.b16 {%0,%1,%2,%3}, [%4];"
                 : "=r"(r0), "=r"(r1), "=r"(r2), "=r"(r3) : "r"(addr));
}
__device__ __forceinline__ void mma16816(float& d0, float& d1, float& d2, float& d3,
                                         uint32_t a0, uint32_t a1, uint32_t a2, uint32_t a3,
                                         uint32_t b0, uint32_t b1) {
    asm volatile("mma.sync.aligned.m16n8k16.row.col.f32.bf16.bf16.f32 "
                 "{%0,%1,%2,%3}, {%4,%5,%6,%7}, {%8,%9}, {%0,%1,%2,%3};"
                 : "+f"(d0), "+f"(d1), "+f"(d2), "+f"(d3)
                 : "r"(a0), "r"(a1), "r"(a2), "r"(a3), "r"(b0), "r"(b1));
}

// smem: STAGES x 4 arrays (Ahi, Alo, Bhi, Blo), each 16 rows x 256B = 4 KB
#define ARR_BYTES   4096
#define STAGE_BYTES 16384     // 4 arrays

__global__ __launch_bounds__(256) void sru_gemm_kernel()
{
    __shared__ __align__(16) char smem[STAGES * STAGE_BYTES];   // 48 KB (static max)
    const uint32_t sbase = (uint32_t)__cvta_generic_to_shared(smem);

    const int tid  = threadIdx.x;
    const int lane = tid & 31;
    const int wid  = tid >> 5;
    const int m_w  = (wid & 1) * 64;   // warp M offset
    const int n_w  = (wid >> 1) * 32;  // warp N offset

    const int bM = blockIdx.y * BM;
    const int bN = blockIdx.x * BN;

    // cp.async mapping: one 16B granule per thread per array
    const int krow  = tid >> 4;        // 0..15
    const int chunk = tid & 15;        // 0..15  (16B chunks of a 256B row)
    const uint32_t dst_off = (uint32_t)(krow * 256 + ((chunk ^ (krow & 7)) << 4));
    const size_t a_src = (size_t)krow * MROW + bM + chunk * 8;
    const size_t b_src = (size_t)krow * NCOL + bN + chunk * 8;

    // ldmatrix per-lane offsets (row = k within BK=16 tile)
    const int l7   = lane & 7;
    const int a_k  = ((lane >> 4) << 3) | l7;        // lanes 16-31: k+8 (A mats 2,3)
    const int a_mh = (lane >> 3) & 1;                // lanes 8-15,24-31: m+8 (A mats 1,3)
    const int b_k  = (((lane >> 3) & 1) << 3) | l7;  // B mats 1,3: k+8
    const int b_nh = (lane >> 4) & 1;                // B mats 2,3: n+8

    const int mwc = m_w >> 3;   // 16B-chunk base of warp M
    const int nwc = n_w >> 3;

    uint32_t offA[4], offB[2];
    #pragma unroll
    for (int mi = 0; mi < 4; mi++)
        offA[mi] = (uint32_t)(a_k * 256 + (((mwc + mi * 2 + a_mh) ^ (a_k & 7)) << 4));
    #pragma unroll
    for (int nj = 0; nj < 2; nj++)
        offB[nj] = (uint32_t)(b_k * 256 + (((nwc + nj * 2 + b_nh) ^ (b_k & 7)) << 4));

    float acc[4][4][4];
    #pragma unroll
    for (int mi = 0; mi < 4; mi++)
        #pragma unroll
        for (int ni = 0; ni < 4; ni++)
            #pragma unroll
            for (int r = 0; r < 4; r++)
                acc[mi][ni][r] = 0.0f;

    auto load_stage = [&](int t, int stage) {
        const size_t kofs = (size_t)t * BK;
        const uint32_t d = sbase + stage * STAGE_BYTES + dst_off;
        cp_async16(d + 0 * ARR_BYTES, g_XhiT + kofs * MROW + a_src);
        cp_async16(d + 1 * ARR_BYTES, g_XloT + kofs * MROW + a_src);
        cp_async16(d + 2 * ARR_BYTES, g_Whi  + kofs * NCOL + b_src);
        cp_async16(d + 3 * ARR_BYTES, g_Wlo  + kofs * NCOL + b_src);
        cp_commit();
    };

    // Prologue: 2 stages in flight
    load_stage(0, 0);
    load_stage(1, 1);

    int slot_next = 2;   // slot for load t+2
    for (int t = 0; t < NT; t++) {
        if (t + 2 < NT) cp_wait<STAGES - 2>();
        else            cp_wait<0>();
        __syncthreads();   // stage t visible; slot_next's old readers all done

        if (t + 2 < NT) {
            load_stage(t + 2, slot_next);
            slot_next = (slot_next == STAGES - 1) ? 0 : slot_next + 1;
        }

        const int cur = t % STAGES;
        const uint32_t sAhi = sbase + cur * STAGE_BYTES;
        const uint32_t sAlo = sAhi + ARR_BYTES;
        const uint32_t sBhi = sAhi + 2 * ARR_BYTES;
        const uint32_t sBlo = sAhi + 3 * ARR_BYTES;

        uint32_t bh[2][4], bl[2][4];
        #pragma unroll
        for (int nj = 0; nj < 2; nj++) {
            ldm_x4_trans(sBhi + offB[nj], bh[nj][0], bh[nj][1], bh[nj][2], bh[nj][3]);
            ldm_x4_trans(sBlo + offB[nj], bl[nj][0], bl[nj][1], bl[nj][2], bl[nj][3]);
        }

        #pragma unroll
        for (int mi = 0; mi < 4; mi++) {
            uint32_t ah[4], al[4];
            ldm_x4_trans(sAhi + offA[mi], ah[0], ah[1], ah[2], ah[3]);
            ldm_x4_trans(sAlo + offA[mi], al[0], al[1], al[2], al[3]);
            #pragma unroll
            for (int nj = 0; nj < 2; nj++) {
                #pragma unroll
                for (int h = 0; h < 2; h++) {       // n8 half -> B regs (2h, 2h+1)
                    const int ni = nj * 2 + h;
                    float* d = acc[mi][ni];
                    // hi*hi + hi*lo + lo*hi  (lo*lo dropped: O(2^-18))
                    mma16816(d[0], d[1], d[2], d[3], ah[0], ah[1], ah[2], ah[3],
                             bh[nj][2 * h], bh[nj][2 * h + 1]);
                    mma16816(d[0], d[1], d[2], d[3], ah[0], ah[1], ah[2], ah[3],
                             bl[nj][2 * h], bl[nj][2 * h + 1]);
                    mma16816(d[0], d[1], d[2], d[3], al[0], al[1], al[2], al[3],
                             bh[nj][2 * h], bh[nj][2 * h + 1]);
                }
            }
        }
        // no tail barrier: slot reuse ordered by next iteration's top barrier
    }

    // Epilogue: streaming stores (g_U is write-once/read-once; keep it out of L2
    // so the W/X cp.async working set stays resident)
    const int r0 = lane >> 2;
    const int c0 = (lane & 3) * 2;
    #pragma unroll
    for (int mi = 0; mi < 4; mi++) {
        #pragma unroll
        for (int ni = 0; ni < 4; ni++) {
            const size_t row = (size_t)(bM + m_w + mi * 16 + r0);
            const size_t col = (size_t)(bN + n_w + ni * 8 + c0);
            stg_cs_f2(g_U + row * NCOL + col,       acc[mi][ni][0], acc[mi][ni][1]);
            stg_cs_f2(g_U + (row + 8) * NCOL + col, acc[mi][ni][2], acc[mi][ni][3]);
        }
    }
}

// ---------------------------------------------------------------------------
// SRU recurrence, chunked software pipeline (CH=8, ping-pong register bufs).
// One thread per (b, j) channel; 32 independent loads (next chunk) are in
// flight while the dependent sigmoid chain computes the current chunk.
//   f = sigmoid(u1 + b_f + c*wc_f); c = (c - u0)*f + u0
//   r = sigmoid(u2 + b_r + c*wc_r); h = (c - xp)*r + xp,  xp = x*sqrt(3)
// ---------------------------------------------------------------------------
#define CH 8

__global__ __launch_bounds__(256) void sru_scan_kernel(
    const float* __restrict__ x,      // (L, B, DIM)
    const float* __restrict__ wc,     // (2*HID)
    const float* __restrict__ bias,   // (2*HID)
    float* __restrict__ h_out,        // (L, B, HID)
    float* __restrict__ c_out,        // (B, HID) or nullptr
    int write_c)
{
    const int idx = blockIdx.x * blockDim.x + threadIdx.x;  // 0..B*HID-1
    const int b = idx / HID;
    const int j = idx - b * HID;

    const float wcf = wc[j];
    const float wcr = wc[HID + j];
    const float bf  = bias[j];
    const float br  = bias[HID + j];
    const float scale_x = 1.7320508075688772f;   // sqrt(1 + 2*exp(0))

    const size_t Ustep = (size_t)BATCH * NCOL;
    const size_t xstep = (size_t)BATCH * DIM;
    const size_t hstep = (size_t)BATCH * HID;

    const float* Uld = g_U + (size_t)b * NCOL + 3 * j;
    const float* xld = x + (size_t)b * DIM + j;
    float*       hst = h_out + (size_t)b * HID + j;

    float c = 0.0f;

    float A0[CH], A1[CH], A2[CH], A3[CH];
    float B0[CH], B1[CH], B2[CH], B3[CH];

    auto load = [&](float* u0, float* u1, float* u2, float* xv, int l0) {
        const float* Up = Uld + (size_t)l0 * Ustep;
        const float* xp = xld + (size_t)l0 * xstep;
        #pragma unroll
        for (int i = 0; i < CH; i++) {
            u0[i] = ldg_cs_f(Up + 0);    // read-once: evict-first
            u1[i] = ldg_cs_f(Up + 1);
            u2[i] = ldg_cs_f(Up + 2);
            xv[i] = xp[0];
            Up += Ustep;
            xp += xstep;
        }
    };

    auto compute = [&](const float* u0, const float* u1, const float* u2,
                       const float* xv) {
        #pragma unroll
        for (int i = 0; i < CH; i++) {
            const float zf = fmaf(c, wcf, u1[i] + bf);
            const float f  = 1.0f / (1.0f + __expf(-zf));
            c = fmaf(f, c - u0[i], u0[i]);

            const float xs = xv[i] * scale_x;
            const float zr = fmaf(c, wcr, u2[i] + br);
            const float r  = 1.0f / (1.0f + __expf(-zr));
            hst[0] = fmaf(r, c - xs, xs);
            hst += hstep;
        }
    };

    load(A0, A1, A2, A3, 0);
    for (int l0 = 0; l0 < L_LEN; l0 += 2 * CH) {
        load(B0, B1, B2, B3, l0 + CH);          // l0+CH <= L_LEN-CH always
        compute(A0, A1, A2, A3);
        if (l0 + 2 * CH < L_LEN)
            load(A0, A1, A2, A3, l0 + 2 * CH);
        compute(B0, B1, B2, B3);
    }

    if (write_c) c_out[idx] = c;
}

// ---------------------------------------------------------------------------
// Launch
// ---------------------------------------------------------------------------
extern "C" void kernel_launch(void* const* d_in, const int* in_sizes, int n_in,
                              void* d_out, int out_size)
{
    const float* x    = (const float*)d_in[0];   // (L, B, DIM)
    const float* w    = (const float*)d_in[1];   // (DIM, 3*HID)
    const float* wc   = (const float*)d_in[2];   // (2*HID)
    const float* bias = (const float*)d_in[3];   // (2*HID)

    float* out = (float*)d_out;
    const long long h_elems = (long long)L_LEN * BATCH * HID;
    const long long c_elems = (long long)BATCH * HID;

    // 1) Split-convert W and transpose-convert X
    {
        const size_t nw = (size_t)DIM * NCOL;
        conv_w_kernel<<<(unsigned)((nw + 255) / 256), 256>>>(w);
        dim3 gx(DIM / 32, MROW / 32);    // (64, 512)
        conv_x_kernel<<<gx, dim3(32, 8)>>>(x);
    }

    // 2) GEMM: U = X @ W (split-bf16, 3-MMA)
    {
        dim3 grid(NCOL / BN, MROW / BM);   // (48, 128)
        sru_gemm_kernel<<<grid, 256>>>();
    }

    // 3) Scan
    {
        const int threads = 256;
        const int blocks = (BATCH * HID) / threads;  // 128
        const int write_c = ((long long)out_size >= h_elems + c_elems) ? 1 : 0;
        float* c_out = write_c ? (out + h_elems) : nullptr;
        sru_scan_kernel<<<blocks, threads>>>(x, wc, bias, out, c_out, write_c);
    }
}

// round 10
// speedup vs baseline: 1.5141x; 1.5141x over previous
#include <cuda_runtime.h>
#include <cuda_fp16.h>
#include <cstdint>

// Problem constants (fixed by the reference)
#define L_LEN   1024
#define BATCH   16
#define DIM     2048            // K
#define HID     2048
#define NCOL    (3 * HID)       // 6144  (N)
#define MROW    (L_LEN * BATCH) // 16384 (M)

// ---------------------------------------------------------------------------
// Device scratch (static __device__ globals: the sanctioned no-alloc path)
// ---------------------------------------------------------------------------
__device__ float  g_U  [(size_t)MROW * NCOL];   // 402.7 MB
__device__ __half g_AhT[(size_t)DIM * MROW];    // X^T hi  [K][M]  64 MB
__device__ __half g_Bh [(size_t)DIM * NCOL];    // W hi    [K][N]  24 MB
__device__ __half g_Bl [(size_t)DIM * NCOL];    // W lo    [K][N]  24 MB

// ---------------------------------------------------------------------------
// PTX helpers
// ---------------------------------------------------------------------------
__device__ __forceinline__ void cp_async16(uint32_t dst, const void* src) {
    asm volatile("cp.async.ca.shared.global [%0], [%1], 16;\n" :: "r"(dst), "l"(src));
}
__device__ __forceinline__ void cp_commit() {
    asm volatile("cp.async.commit_group;\n" ::: "memory");
}
template<int N> __device__ __forceinline__ void cp_wait() {
    asm volatile("cp.async.wait_group %0;\n" :: "n"(N) : "memory");
}
__device__ __forceinline__ void ldm_x4_trans(uint32_t addr, uint32_t& r0, uint32_t& r1,
                                             uint32_t& r2, uint32_t& r3) {
    asm volatile("ldmatrix.sync.aligned.m8n8.x4.trans.shared.b16 {%0,%1,%2,%3}, [%4];"
                 : "=r"(r0), "=r"(r1), "=r"(r2), "=r"(r3) : "r"(addr));
}
__device__ __forceinline__ void mma16816(float& d0, float& d1, float& d2, float& d3,
                                         uint32_t a0, uint32_t a1, uint32_t a2, uint32_t a3,
                                         uint32_t b0, uint32_t b1) {
    asm volatile("mma.sync.aligned.m16n8k16.row.col.f32.f16.f16.f32 "
                 "{%0,%1,%2,%3}, {%4,%5,%6,%7}, {%8,%9}, {%0,%1,%2,%3};"
                 : "+f"(d0), "+f"(d1), "+f"(d2), "+f"(d3)
                 : "r"(a0), "r"(a1), "r"(a2), "r"(a3), "r"(b0), "r"(b1));
}
__device__ __forceinline__ void stg_cs_f2(float* p, float a, float b) {
    asm volatile("st.global.cs.v2.f32 [%0], {%1, %2};" :: "l"(p), "f"(a), "f"(b) : "memory");
}
__device__ __forceinline__ float ldg_cs_f(const float* p) {
    float v;
    asm volatile("ld.global.cs.f32 %0, [%1];" : "=f"(v) : "l"(p));
    return v;
}
__device__ __forceinline__ uint32_t hpack(__half a, __half b) {
    __half2 t = __halves2half2(a, b);
    return reinterpret_cast<uint32_t&>(t);
}

// ---------------------------------------------------------------------------
// conv_x: X [M][K] fp32 -> g_AhT [K][M] fp16 (transpose, hi only)
// ---------------------------------------------------------------------------
__global__ __launch_bounds__(256) void conv_x_kernel(const float* __restrict__ x)
{
    __shared__ float t[32][33];
    const int k0 = blockIdx.x * 32;
    const int m0 = blockIdx.y * 32;
    const int tx = threadIdx.x;        // 0..31
    const int ty = threadIdx.y;        // 0..7

    #pragma unroll
    for (int i = 0; i < 4; i++)
        t[ty + 8*i][tx] = x[(size_t)(m0 + ty + 8*i) * DIM + k0 + tx];
    __syncthreads();

    #pragma unroll
    for (int i = 0; i < 4; i++) {
        float v = t[tx][ty + 8*i];                 // = x[m0+tx][k0+ty+8i]
        g_AhT[(size_t)(k0 + ty + 8*i) * MROW + m0 + tx] = __float2half_rn(v);
    }
}

// ---------------------------------------------------------------------------
// conv_w: W [K][N] fp32 -> g_Bh/g_Bl [K][N] fp16 (split, no transpose)
// ---------------------------------------------------------------------------
__global__ __launch_bounds__(256) void conv_w_kernel(const float* __restrict__ w)
{
    const size_t i = (size_t)blockIdx.x * 256 + threadIdx.x;   // float4 index
    const float4 v = reinterpret_cast<const float4*>(w)[i];
    __half h0 = __float2half_rn(v.x), h1 = __float2half_rn(v.y);
    __half h2 = __float2half_rn(v.z), h3 = __float2half_rn(v.w);
    __half l0 = __float2half_rn(v.x - __half2float(h0));
    __half l1 = __float2half_rn(v.y - __half2float(h1));
    __half l2 = __float2half_rn(v.z - __half2float(h2));
    __half l3 = __float2half_rn(v.w - __half2float(h3));
    reinterpret_cast<uint2*>(g_Bh)[i] = make_uint2(hpack(h0,h1), hpack(h2,h3));
    reinterpret_cast<uint2*>(g_Bl)[i] = make_uint2(hpack(l0,l1), hpack(l2,l3));
}

// ---------------------------------------------------------------------------
// 2-term fp16 GEMM: g_U[M][N] = X[M][K]*W[K][N],  U = Xh*(Wh + Wl)
// BM=BN=128, BK=32, 256 threads (8 warps, 64x32 warp tiles),
// 3-stage cp.async pipeline, XOR-swizzled smem, ldmatrix.trans + mma.m16n8k16.
// smem per stage: A 8KB + Bh 8KB + Bl 8KB = 24KB; 3 stages = 72KB (dynamic).
// ---------------------------------------------------------------------------
#define BM 128
#define BN 128
#define BK 32
#define NT (DIM / BK)   // 64
#define STAGES 3
#define ARR_BYTES   8192       // 32 rows x 256B
#define STAGE_BYTES (3 * ARR_BYTES)
#define GEMM_SMEM   (STAGES * STAGE_BYTES)   // 73728

__global__ __launch_bounds__(256, 2) void sru_gemm_kernel()
{
    extern __shared__ __align__(16) char smem[];
    const uint32_t sbase = (uint32_t)__cvta_generic_to_shared(smem);

    const int tid  = threadIdx.x;
    const int lane = tid & 31;
    const int wid  = tid >> 5;
    const int m_w  = (wid & 1) * 64;   // warp M offset
    const int n_w  = (wid >> 1) * 32;  // warp N offset

    const int bM = blockIdx.y * BM;
    const int bN = blockIdx.x * BN;

    // cp.async mapping: 32 rows x 16 granules = 512 granules per array; 2/thread
    const int kr0 = tid >> 3;                 // rows 0..31
    const int g0  = tid & 7;                  // granules 0..7
    const int g1  = g0 + 8;                   // granules 8..15
    const uint32_t d_off0 = (uint32_t)(kr0 * 256 + ((g0 ^ (kr0 & 7)) << 4));
    const uint32_t d_off1 = (uint32_t)(kr0 * 256 + ((g1 ^ (kr0 & 7)) << 4));
    const size_t a_s0 = (size_t)kr0 * MROW + bM + g0 * 8;
    const size_t a_s1 = (size_t)kr0 * MROW + bM + g1 * 8;
    const size_t b_s0 = (size_t)kr0 * NCOL + bN + g0 * 8;
    const size_t b_s1 = (size_t)kr0 * NCOL + bN + g1 * 8;

    // ldmatrix per-lane offsets (within a 16-row k-chunk; validated mapping)
    const int l7   = lane & 7;
    const int a_k  = ((lane >> 4) << 3) | l7;        // lanes 16-31: k+8 (A mats 2,3)
    const int a_mh = (lane >> 3) & 1;                // m+8 for mats 1,3
    const int b_k  = (((lane >> 3) & 1) << 3) | l7;  // B mats 1,3: k+8
    const int b_nh = (lane >> 4) & 1;                // n+8 for mats 2,3

    const int mwc = m_w >> 3;
    const int nwc = n_w >> 3;

    uint32_t offA[4], offB[2];
    #pragma unroll
    for (int mi = 0; mi < 4; mi++)
        offA[mi] = (uint32_t)(a_k * 256 + (((mwc + mi * 2 + a_mh) ^ (a_k & 7)) << 4));
    #pragma unroll
    for (int nj = 0; nj < 2; nj++)
        offB[nj] = (uint32_t)(b_k * 256 + (((nwc + nj * 2 + b_nh) ^ (b_k & 7)) << 4));

    float acc[4][4][4];
    #pragma unroll
    for (int mi = 0; mi < 4; mi++)
        #pragma unroll
        for (int ni = 0; ni < 4; ni++)
            #pragma unroll
            for (int r = 0; r < 4; r++)
                acc[mi][ni][r] = 0.0f;

    auto load_stage = [&](int t, int stage) {
        const size_t kofs = (size_t)t * BK;
        const uint32_t d = sbase + stage * STAGE_BYTES;
        cp_async16(d + d_off0,                 g_AhT + kofs * MROW + a_s0);
        cp_async16(d + d_off1,                 g_AhT + kofs * MROW + a_s1);
        cp_async16(d + ARR_BYTES + d_off0,     g_Bh  + kofs * NCOL + b_s0);
        cp_async16(d + ARR_BYTES + d_off1,     g_Bh  + kofs * NCOL + b_s1);
        cp_async16(d + 2*ARR_BYTES + d_off0,   g_Bl  + kofs * NCOL + b_s0);
        cp_async16(d + 2*ARR_BYTES + d_off1,   g_Bl  + kofs * NCOL + b_s1);
        cp_commit();
    };

    load_stage(0, 0);
    load_stage(1, 1);

    int slot_next = 2;   // slot for load t+2
    for (int t = 0; t < NT; t++) {
        if (t + 2 < NT) cp_wait<STAGES - 2>();
        else            cp_wait<0>();
        __syncthreads();   // stage t visible; slot_next's old readers done

        if (t + 2 < NT) {
            load_stage(t + 2, slot_next);
            slot_next = (slot_next == STAGES - 1) ? 0 : slot_next + 1;
        }

        const uint32_t sA  = sbase + (t % STAGES) * STAGE_BYTES;
        const uint32_t sBh = sA + ARR_BYTES;
        const uint32_t sBl = sA + 2*ARR_BYTES;

        #pragma unroll
        for (int ch = 0; ch < 2; ch++) {           // two K=16 chunks in BK=32
            const uint32_t co = (uint32_t)(ch * 4096);   // 16 rows * 256B

            uint32_t bh[2][4], bl[2][4];
            #pragma unroll
            for (int nj = 0; nj < 2; nj++) {
                ldm_x4_trans(sBh + co + offB[nj], bh[nj][0], bh[nj][1], bh[nj][2], bh[nj][3]);
                ldm_x4_trans(sBl + co + offB[nj], bl[nj][0], bl[nj][1], bl[nj][2], bl[nj][3]);
            }

            #pragma unroll
            for (int mi = 0; mi < 4; mi++) {
                uint32_t ah[4];
                ldm_x4_trans(sA + co + offA[mi], ah[0], ah[1], ah[2], ah[3]);
                #pragma unroll
                for (int nj = 0; nj < 2; nj++) {
                    #pragma unroll
                    for (int h = 0; h < 2; h++) {  // n8 half -> B regs (2h, 2h+1)
                        const int ni = nj * 2 + h;
                        float* d = acc[mi][ni];
                        // xh*wh + xh*wl  (residual xl dropped: ~2^-12 rel)
                        mma16816(d[0], d[1], d[2], d[3], ah[0], ah[1], ah[2], ah[3],
                                 bh[nj][2*h], bh[nj][2*h + 1]);
                        mma16816(d[0], d[1], d[2], d[3], ah[0], ah[1], ah[2], ah[3],
                                 bl[nj][2*h], bl[nj][2*h + 1]);
                    }
                }
            }
        }
        // no tail barrier: slot reuse ordered by next iteration's top barrier
    }

    // Epilogue: streaming stores (g_U is write-once/read-once)
    const int r0 = lane >> 2;
    const int c0 = (lane & 3) * 2;
    #pragma unroll
    for (int mi = 0; mi < 4; mi++) {
        #pragma unroll
        for (int ni = 0; ni < 4; ni++) {
            const size_t row = (size_t)(bM + m_w + mi * 16 + r0);
            const size_t col = (size_t)(bN + n_w + ni * 8 + c0);
            stg_cs_f2(g_U + row * NCOL + col,       acc[mi][ni][0], acc[mi][ni][1]);
            stg_cs_f2(g_U + (row + 8) * NCOL + col, acc[mi][ni][2], acc[mi][ni][3]);
        }
    }
}

// ---------------------------------------------------------------------------
// SRU recurrence, chunked software pipeline (CH=16, ping-pong register bufs).
//   f = sigmoid(u1 + b_f + c*wc_f); c = (c - u0)*f + u0
//   r = sigmoid(u2 + b_r + c*wc_r); h = (c - xp)*r + xp,  xp = x*sqrt(3)
// ---------------------------------------------------------------------------
#define CH 16

__global__ __launch_bounds__(256) void sru_scan_kernel(
    const float* __restrict__ x,      // (L, B, DIM)
    const float* __restrict__ wc,     // (2*HID)
    const float* __restrict__ bias,   // (2*HID)
    float* __restrict__ h_out,        // (L, B, HID)
    float* __restrict__ c_out,        // (B, HID) or nullptr
    int write_c)
{
    const int idx = blockIdx.x * blockDim.x + threadIdx.x;  // 0..B*HID-1
    const int b = idx / HID;
    const int j = idx - b * HID;

    const float wcf = wc[j];
    const float wcr = wc[HID + j];
    const float bf  = bias[j];
    const float br  = bias[HID + j];
    const float scale_x = 1.7320508075688772f;   // sqrt(1 + 2*exp(0))

    const size_t Ustep = (size_t)BATCH * NCOL;
    const size_t xstep = (size_t)BATCH * DIM;
    const size_t hstep = (size_t)BATCH * HID;

    const float* Uld = g_U + (size_t)b * NCOL + 3 * j;
    const float* xld = x + (size_t)b * DIM + j;
    float*       hst = h_out + (size_t)b * HID + j;

    float c = 0.0f;

    float A0[CH], A1[CH], A2[CH], A3[CH];
    float B0[CH], B1[CH], B2[CH], B3[CH];

    auto load = [&](float* u0, float* u1, float* u2, float* xv, int l0) {
        const float* Up = Uld + (size_t)l0 * Ustep;
        const float* xp = xld + (size_t)l0 * xstep;
        #pragma unroll
        for (int i = 0; i < CH; i++) {
            u0[i] = ldg_cs_f(Up + 0);    // read-once: evict-first
            u1[i] = ldg_cs_f(Up + 1);
            u2[i] = ldg_cs_f(Up + 2);
            xv[i] = xp[0];
            Up += Ustep;
            xp += xstep;
        }
    };

    auto compute = [&](const float* u0, const float* u1, const float* u2,
                       const float* xv) {
        #pragma unroll
        for (int i = 0; i < CH; i++) {
            const float zf = fmaf(c, wcf, u1[i] + bf);
            const float f  = 1.0f / (1.0f + __expf(-zf));
            c = fmaf(f, c - u0[i], u0[i]);

            const float xs = xv[i] * scale_x;
            const float zr = fmaf(c, wcr, u2[i] + br);
            const float r  = 1.0f / (1.0f + __expf(-zr));
            hst[0] = fmaf(r, c - xs, xs);
            hst += hstep;
        }
    };

    load(A0, A1, A2, A3, 0);
    for (int l0 = 0; l0 < L_LEN; l0 += 2 * CH) {
        load(B0, B1, B2, B3, l0 + CH);
        compute(A0, A1, A2, A3);
        if (l0 + 2 * CH < L_LEN)
            load(A0, A1, A2, A3, l0 + 2 * CH);
        compute(B0, B1, B2, B3);
    }

    if (write_c) c_out[idx] = c;
}

// ---------------------------------------------------------------------------
// Launch
// ---------------------------------------------------------------------------
extern "C" void kernel_launch(void* const* d_in, const int* in_sizes, int n_in,
                              void* d_out, int out_size)
{
    const float* x    = (const float*)d_in[0];   // (L, B, DIM)
    const float* w    = (const float*)d_in[1];   // (DIM, 3*HID)
    const float* wc   = (const float*)d_in[2];   // (2*HID)
    const float* bias = (const float*)d_in[3];   // (2*HID)

    float* out = (float*)d_out;
    const long long h_elems = (long long)L_LEN * BATCH * HID;
    const long long c_elems = (long long)BATCH * HID;

    // Unconditional (no static guards allowed); proven capture-safe in R6.
    cudaFuncSetAttribute(sru_gemm_kernel,
                         cudaFuncAttributeMaxDynamicSharedMemorySize, GEMM_SMEM);

    // 1) Transpose+convert X (hi only), split-convert W
    {
        dim3 gx(DIM / 32, MROW / 32);    // (64, 512)
        conv_x_kernel<<<gx, dim3(32, 8)>>>(x);
        conv_w_kernel<<<(unsigned)(((size_t)DIM * NCOL / 4) / 256), 256>>>(w);
    }

    // 2) GEMM: U = X @ W (fp16 2-term)
    {
        dim3 grid(NCOL / BN, MROW / BM);   // (48, 128)
        sru_gemm_kernel<<<grid, 256, GEMM_SMEM>>>();
    }

    // 3) Scan
    {
        const int threads = 256;
        const int blocks = (BATCH * HID) / threads;  // 128
        const int write_c = ((long long)out_size >= h_elems + c_elems) ? 1 : 0;
        float* c_out = write_c ? (out + h_elems) : nullptr;
        sru_scan_kernel<<<blocks, threads>>>(x, wc, bias, out, c_out, write_c);
    }
}